// round 1
// baseline (speedup 1.0000x reference)
#include <cuda_runtime.h>

typedef unsigned long long ull;

constexpr int Bn = 128;
constexpr int Tn = 1024;
constexpr int In = 256;
constexpr int Hn = 512;

__device__ __forceinline__ ull pack2f(float x, float y) {
    ull r; asm("mov.b64 %0, {%1, %2};" : "=l"(r) : "f"(x), "f"(y)); return r;
}
__device__ __forceinline__ float2 unpack2f(ull v) {
    float2 r; asm("mov.b64 {%0, %1}, %2;" : "=f"(r.x), "=f"(r.y) : "l"(v)); return r;
}
__device__ __forceinline__ ull splat2f(float x) {
    ull r; asm("mov.b64 %0, {%1, %1};" : "=l"(r) : "f"(x)); return r;
}
__device__ __forceinline__ void ffma2(ull& a, ull x, ull y) {
    asm("fma.rn.f32x2 %0, %1, %2, %0;" : "+l"(a) : "l"(x), "l"(y));
}
__device__ __forceinline__ float sigmoidf_fast(float z) {
    return __fdividef(1.0f, 1.0f + __expf(-z));
}

// ---------------------------------------------------------------------------
// Kernel 1: igates[m][n] = sum_k X[m][k] * Wi[n][k] + bi[n]
//   M = Bn*Tn = 131072, N = Hn = 512, K = In = 256. Written into d_out[B,T,H].
//   64x64 block tile, 4x4 thread tile, BK=32, padded smem.
// ---------------------------------------------------------------------------
__global__ __launch_bounds__(256) void igates_kernel(
    const float* __restrict__ X,
    const float* __restrict__ Wi,
    const float* __restrict__ bi,
    float* __restrict__ out)
{
    __shared__ float Xs[64][33];
    __shared__ float Ws[64][33];

    const int tid = threadIdx.x;
    const int tx = tid & 15;       // n micro-tile (0..15)
    const int ty = tid >> 4;       // m micro-tile (0..15)
    const int m0 = blockIdx.y * 64;
    const int n0 = blockIdx.x * 64;

    float acc[4][4] = {};

    for (int k0 = 0; k0 < In; k0 += 32) {
        // Cooperative load: 64 rows x 32 cols per matrix = 512 float4s; 2 per thread.
        #pragma unroll
        for (int hh = 0; hh < 2; hh++) {
            int idx = tid + 256 * hh;     // 0..511
            int r   = idx >> 3;           // 0..63
            int c4  = idx & 7;            // 0..7
            float4 v = *(const float4*)(X + (size_t)(m0 + r) * In + k0 + c4 * 4);
            Xs[r][c4*4+0] = v.x; Xs[r][c4*4+1] = v.y;
            Xs[r][c4*4+2] = v.z; Xs[r][c4*4+3] = v.w;
            float4 w = *(const float4*)(Wi + (size_t)(n0 + r) * In + k0 + c4 * 4);
            Ws[r][c4*4+0] = w.x; Ws[r][c4*4+1] = w.y;
            Ws[r][c4*4+2] = w.z; Ws[r][c4*4+3] = w.w;
        }
        __syncthreads();

        #pragma unroll
        for (int k = 0; k < 32; k++) {
            float a[4], b[4];
            #pragma unroll
            for (int i = 0; i < 4; i++) a[i] = Xs[ty*4 + i][k];
            #pragma unroll
            for (int j = 0; j < 4; j++) b[j] = Ws[tx*4 + j][k];
            #pragma unroll
            for (int i = 0; i < 4; i++)
                #pragma unroll
                for (int j = 0; j < 4; j++)
                    acc[i][j] += a[i] * b[j];
        }
        __syncthreads();
    }

    float4 bv = *(const float4*)(bi + n0 + tx * 4);
    #pragma unroll
    for (int i = 0; i < 4; i++) {
        float4 o = make_float4(acc[i][0] + bv.x, acc[i][1] + bv.y,
                               acc[i][2] + bv.z, acc[i][3] + bv.w);
        *(float4*)(out + (size_t)(m0 + ty*4 + i) * Hn + n0 + tx * 4) = o;
    }
}

// ---------------------------------------------------------------------------
// Kernel 2: persistent clustered recurrence.
//   Grid = 128 CTAs = 16 independent clusters x 8 CTAs. Cluster g owns batch
//   rows [8g, 8g+8); CTA c of the cluster owns output columns [64c, 64c+64).
//   Per step: each CTA computes its [8 x 64] slice of h_new = sigmoid(ig + h@Wh^T + bh),
//   writes it into d_out[b][t][:] (which doubles as the h exchange buffer),
//   then barrier.cluster. Next step every CTA pulls the full h row (16 KB)
//   back from L2 with __ldcg (L1 is not coherent across SMs).
//   Wh slice lives entirely in registers: thread (jj = t&63, rq = t>>6) holds
//   Wh[j][rq*128 .. rq*128+127] (128 regs). Row-pairs are accumulated with
//   packed fma.rn.f32x2.
// ---------------------------------------------------------------------------
__global__ __launch_bounds__(256, 1) __cluster_dims__(8, 1, 1)
void rnn_kernel(
    float* __restrict__ out,
    const float* __restrict__ hidden,
    const float* __restrict__ Wh,
    const float* __restrict__ bh)
{
    __shared__ ull hp[4][512];        // h packed as row-pairs: hp[rp][k] = (h[2rp][k], h[2rp+1][k])
    __shared__ ull part[4][4][64];    // partials: [k-slice][row-pair][jj]

    const int tid   = threadIdx.x;
    const int jj    = tid & 63;       // local output column
    const int rq    = tid >> 6;       // 0..3: k-slice in compute, row-pair in epilogue
    const int crank = blockIdx.x & 7;         // cluster ctarank (1-D cluster)
    const int gbase = (blockIdx.x >> 3) * 8;  // batch base of this cluster
    const int j     = crank * 64 + jj;        // global output column
    const float bhj = bh[j];
    const int b0    = gbase + 2 * rq;         // this thread's epilogue batch rows (b0, b0+1)

    float* __restrict__ hl = out + (size_t)Bn * Tn * Hn;   // h_last region

    // Load this thread's Wh slice into registers: Wh[j][rq*128 .. +127]
    float4 W4[32];
    {
        const float4* wp = (const float4*)(Wh + (size_t)j * Hn + rq * 128);
        #pragma unroll
        for (int u = 0; u < 32; u++) W4[u] = wp[u];
    }

    for (int t = 0; t < Tn; t++) {
        // ---- stage h (row t-1, or the initial hidden state) into shared ----
        if (t == 0) {
            for (int i = tid; i < 2048; i += 256) {
                int rp = i >> 9, k = i & 511;
                int r0 = gbase + 2 * rp;
                hp[rp][k] = pack2f(hidden[r0 * Hn + k], hidden[(r0 + 1) * Hn + k]);
            }
        } else {
            const size_t toff = (size_t)(t - 1) * Hn;
            for (int i = tid; i < 2048; i += 256) {
                int rp = i >> 9, k = i & 511;
                int r0 = gbase + 2 * rp;
                float x0 = __ldcg(out + (size_t)r0       * (Tn * Hn) + toff + k);
                float x1 = __ldcg(out + (size_t)(r0 + 1) * (Tn * Hn) + toff + k);
                hp[rp][k] = pack2f(x0, x1);
            }
        }
        // Prefetch this thread's igate values (independent of h -> hides L2 latency)
        const float ig0 = __ldcg(out + (size_t)b0       * (Tn * Hn) + (size_t)t * Hn + j);
        const float ig1 = __ldcg(out + (size_t)(b0 + 1) * (Tn * Hn) + (size_t)t * Hn + j);
        __syncthreads();

        // ---- compute: partial dot over this thread's 128-k slice, 4 row-pairs ----
        ull a0 = 0, a1 = 0, a2 = 0, a3 = 0;
        const ull* __restrict__ h0p = &hp[0][rq * 128];
        const ull* __restrict__ h1p = &hp[1][rq * 128];
        const ull* __restrict__ h2p = &hp[2][rq * 128];
        const ull* __restrict__ h3p = &hp[3][rq * 128];
        #pragma unroll
        for (int u = 0; u < 32; u++) {
            #pragma unroll
            for (int q = 0; q < 4; q++) {
                float w = (q == 0) ? W4[u].x : (q == 1) ? W4[u].y
                        : (q == 2) ? W4[u].z : W4[u].w;
                ull w2 = splat2f(w);
                int k = u * 4 + q;
                ffma2(a0, w2, h0p[k]);
                ffma2(a1, w2, h1p[k]);
                ffma2(a2, w2, h2p[k]);
                ffma2(a3, w2, h3p[k]);
            }
        }
        part[rq][0][jj] = a0;
        part[rq][1][jj] = a1;
        part[rq][2][jj] = a2;
        part[rq][3][jj] = a3;
        __syncthreads();

        // ---- epilogue: reduce 4 k-slices, add ig + bias, sigmoid, store ----
        float2 p0 = unpack2f(part[0][rq][jj]);
        float2 p1 = unpack2f(part[1][rq][jj]);
        float2 p2 = unpack2f(part[2][rq][jj]);
        float2 p3 = unpack2f(part[3][rq][jj]);
        float zx = p0.x + p1.x + p2.x + p3.x + ig0 + bhj;
        float zy = p0.y + p1.y + p2.y + p3.y + ig1 + bhj;
        float h0v = sigmoidf_fast(zx);
        float h1v = sigmoidf_fast(zy);
        out[(size_t)b0       * (Tn * Hn) + (size_t)t * Hn + j] = h0v;
        out[(size_t)(b0 + 1) * (Tn * Hn) + (size_t)t * Hn + j] = h1v;
        if (t == Tn - 1) {
            hl[b0 * Hn + j]       = h0v;
            hl[(b0 + 1) * Hn + j] = h1v;
        }

        // ---- cluster barrier: release our h-slice stores to cluster peers ----
        asm volatile("barrier.cluster.arrive.aligned;" ::: "memory");
        asm volatile("barrier.cluster.wait.aligned;"   ::: "memory");
    }
}

// ---------------------------------------------------------------------------
// Launch
// ---------------------------------------------------------------------------
extern "C" void kernel_launch(void* const* d_in, const int* in_sizes, int n_in,
                              void* d_out, int out_size)
{
    const float* x      = (const float*)d_in[0];   // [B, T, I]
    const float* hidden = (const float*)d_in[1];   // [B, H]
    const float* Wi     = (const float*)d_in[2];   // [H, I]
    const float* bi     = (const float*)d_in[3];   // [H]
    const float* Wh     = (const float*)d_in[4];   // [H, H]
    const float* bh     = (const float*)d_in[5];   // [H]
    float* out = (float*)d_out;                    // [B,T,H] output then [B,H] h_last

    // 1) igates = x @ Wi^T + bi, written into the output region
    dim3 g1(Hn / 64, (Bn * Tn) / 64);
    igates_kernel<<<g1, 256>>>(x, Wi, bi, out);

    // 2) persistent clustered recurrence (16 independent clusters of 8 CTAs)
    rnn_kernel<<<128, 256>>>(out, hidden, Wh, bh);
}